// round 4
// baseline (speedup 1.0000x reference)
#include <cuda_runtime.h>

typedef unsigned long long u64;

#define HID 16
#define TSEQ 64
#define NB 2048
#define MAX_STEPS 16
#define FULLM 0xffffffffu

// ---------------- packed fp32x2 + MUFU helpers ----------------
__device__ __forceinline__ u64 ffma2(u64 a, u64 b, u64 c) {
    u64 d; asm("fma.rn.f32x2 %0, %1, %2, %3;" : "=l"(d) : "l"(a), "l"(b), "l"(c)); return d;
}
__device__ __forceinline__ u64 fmul2(u64 a, u64 b) {
    u64 d; asm("mul.rn.f32x2 %0, %1, %2;" : "=l"(d) : "l"(a), "l"(b)); return d;
}
__device__ __forceinline__ u64 fadd2(u64 a, u64 b) {
    u64 d; asm("add.rn.f32x2 %0, %1, %2;" : "=l"(d) : "l"(a), "l"(b)); return d;
}
__device__ __forceinline__ float2 unpk2(u64 a) {
    float lo, hi; asm("mov.b64 {%0, %1}, %2;" : "=f"(lo), "=f"(hi) : "l"(a));
    return make_float2(lo, hi);
}
__device__ __forceinline__ u64 pk2(float lo, float hi) {
    u64 d; asm("mov.b64 %0, {%1, %2};" : "=l"(d) : "f"(lo), "f"(hi)); return d;
}
__device__ __forceinline__ float ex2a(float x){ float r; asm("ex2.approx.f32 %0, %1;" : "=f"(r) : "f"(x)); return r; }
__device__ __forceinline__ float rcpa(float x){ float r; asm("rcp.approx.f32 %0, %1;" : "=f"(r) : "f"(x)); return r; }
__device__ __forceinline__ float lg2a(float x){ float r; asm("lg2.approx.f32 %0, %1;" : "=f"(r) : "f"(x)); return r; }

#define TWO_LOG2E 2.885390081777927f

// tanh(z + b) with prescaled bias bs = TWO_LOG2E*b:
// tanh(x) = 1 - 2/(exp(2x)+1),  exp(2x) = ex2(TWO_LOG2E*z + bs)
__device__ __forceinline__ float tanh_pre(float z, float bs){
    float e = ex2a(fmaf(z, TWO_LOG2E, bs));
    return fmaf(-2.0f, rcpa(e + 1.0f), 1.0f);
}
// sigmoid(x) = 1/(1+exp(-x))
__device__ __forceinline__ float fast_sigmoid(float x){
    float e = ex2a(x * -1.4426950408889634f);
    return rcpa(e + 1.0f);
}

// broadcast 16 per-lane scalars (one per hidden unit, within a 16-lane half)
// into 8 packed f32x2 registers on every lane
__device__ __forceinline__ void bcast16(float a, u64* p){
#pragma unroll
    for (int j = 0; j < 8; ++j) {
        float lo = __shfl_sync(FULLM, a, 2*j,     16);
        float hi = __shfl_sync(FULLM, a, 2*j + 1, 16);
        p[j] = pk2(lo, hi);
    }
}

// dot of packed broadcast vector vs register-resident packed weight row
__device__ __forceinline__ float dot16p(const u64* v, const u64* w){
    u64 s0 = fmul2(v[0], w[0]);
    u64 s1 = fmul2(v[1], w[1]);
    u64 s2 = fmul2(v[2], w[2]);
    u64 s3 = fmul2(v[3], w[3]);
    s0 = ffma2(v[4], w[4], s0);
    s1 = ffma2(v[5], w[5], s1);
    s2 = ffma2(v[6], w[6], s2);
    s3 = ffma2(v[7], w[7], s3);
    u64 t0 = fadd2(s0, s1);
    u64 t1 = fadd2(s2, s3);
    u64 t2 = fadd2(t0, t1);
    float2 f = unpk2(t2);
    return f.x + f.y;
}

__device__ __forceinline__ void load_row16(const float* __restrict__ base, u64* wp){
    const float4* p = (const float4*)base;
#pragma unroll
    for (int k = 0; k < 4; ++k) {
        float4 f = p[k];
        wp[2*k]   = pk2(f.x, f.y);
        wp[2*k+1] = pk2(f.z, f.w);
    }
}

// f(v) = w3 @ tanh(w2 @ tanh(w1 @ v + b1) + b2) + b3, component owned by this lane.
__device__ __forceinline__ float f_eval(float a,
                                        const u64* w1p, const u64* w2p, const u64* w3p,
                                        float b1s, float b2s, float b3v){
    u64 p[8];
    bcast16(a, p);
    float h1 = tanh_pre(dot16p(p, w1p), b1s);
    bcast16(h1, p);
    float h2 = tanh_pre(dot16p(p, w2p), b2s);
    bcast16(h2, p);
    return dot16p(p, w3p) + b3v;
}

__global__ void __launch_bounds__(32) ode_rnn_kernel(
    const float* __restrict__ x_seq,
    const float* __restrict__ w1, const float* __restrict__ b1,
    const float* __restrict__ w2, const float* __restrict__ b2,
    const float* __restrict__ w3, const float* __restrict__ b3,
    const float* __restrict__ gwih, const float* __restrict__ gwhh,
    const float* __restrict__ gb,  const float* __restrict__ gbn,
    const float* __restrict__ pw,  const float* __restrict__ pb,
    float* __restrict__ out)
{
    const int lane = threadIdx.x;
    const int l = lane & 15;          // hidden component
    const int s = lane >> 4;          // sample within warp (0/1)
    const int b = blockIdx.x * 2 + s;

    // register-resident weights (rows owned by this lane)
    u64 w1p[8], w2p[8], w3p[8], whr[8], whz[8], whn[8];
    load_row16(w1 + l*16, w1p);
    load_row16(w2 + l*16, w2p);
    load_row16(w3 + l*16, w3p);
    load_row16(gwhh + l*16,      whr);
    load_row16(gwhh + (16+l)*16, whz);
    load_row16(gwhh + (32+l)*16, whn);
    const float b1s = b1[l] * TWO_LOG2E;
    const float b2s = b2[l] * TWO_LOG2E;
    const float b3v = b3[l];
    const float wr0 = gwih[l*2],      wr1 = gwih[l*2+1];
    const float wz0 = gwih[(16+l)*2], wz1 = gwih[(16+l)*2+1];
    const float wn0 = gwih[(32+l)*2], wn1 = gwih[(32+l)*2+1];
    const float gbr = gb[l], gbz = gb[16+l], gbnn = gb[32+l];
    const float bnv = gbn[l];
    const float pwv = pw[l];
    const float pbv = pb[0];

    float y = 0.0f;
    const float* xb = x_seq + (size_t)b * (TSEQ*2);

#pragma unroll 1
    for (int ts = 0; ts < TSEQ; ++ts) {
        const float x0 = xb[ts*2 + 0];
        const float x1 = xb[ts*2 + 1];
        // GRU input gates depend only on x_t — precompute up front
        const float ir  = fmaf(x0, wr0, fmaf(x1, wr1, gbr));
        const float iz  = fmaf(x0, wz0, fmaf(x1, wz1, gbz));
        const float inn = fmaf(x0, wn0, fmaf(x1, wn1, gbnn));

        // ---- adaptive Tsit5, t: 0 -> 1 ----
        float t = 0.0f, dt = 1.0f;
        // FSAL: k1 computed once; thereafter k1 = accept ? k7 : k1 (bit-exact)
        float k1 = f_eval(y, w1p, w2p, w3p, b1s, b2s, b3v);
#pragma unroll 1
        for (int it = 0; it < MAX_STEPS; ++it) {
            float dt_c = fminf(dt, 1.0f - t);

            float a = 0.161f * k1;
            float k2 = f_eval(fmaf(dt_c, a, y), w1p, w2p, w3p, b1s, b2s, b3v);
            a = fmaf(0.335480655492357f, k2, -0.008480655492356989f * k1);
            float k3 = f_eval(fmaf(dt_c, a, y), w1p, w2p, w3p, b1s, b2s, b3v);
            a = 2.8971530571054935f * k1;
            a = fmaf(-6.359448489975075f, k2, a);
            a = fmaf(4.3622954328695815f, k3, a);
            float k4 = f_eval(fmaf(dt_c, a, y), w1p, w2p, w3p, b1s, b2s, b3v);
            a = 5.325864828439257f * k1;
            a = fmaf(-11.748883564062828f, k2, a);
            a = fmaf(7.4955393428898365f, k3, a);
            a = fmaf(-0.09249506636175525f, k4, a);
            float k5 = f_eval(fmaf(dt_c, a, y), w1p, w2p, w3p, b1s, b2s, b3v);
            a = 5.86145544294642f * k1;
            a = fmaf(-12.92096931784711f, k2, a);
            a = fmaf(8.159367898576159f, k3, a);
            a = fmaf(-0.071584973281401f, k4, a);
            a = fmaf(-0.028269050394068383f, k5, a);
            float k6 = f_eval(fmaf(dt_c, a, y), w1p, w2p, w3p, b1s, b2s, b3v);
            a = 0.09646076681806523f * k1;
            a = fmaf(0.01f, k2, a);
            a = fmaf(0.4798896504144996f, k3, a);
            a = fmaf(1.379008574103742f, k4, a);
            a = fmaf(-3.290069515436081f, k5, a);
            a = fmaf(2.324710524099774f, k6, a);
            float y_new = fmaf(dt_c, a, y);
            float k7 = f_eval(y_new, w1p, w2p, w3p, b1s, b2s, b3v);

            a = -0.001780011052225777f * k1;
            a = fmaf(-0.0008164344596567469f, k2, a);
            a = fmaf(0.007880878010261995f, k3, a);
            a = fmaf(-0.1447110071732629f, k4, a);
            a = fmaf(0.5823571654525552f, k5, a);
            a = fmaf(-0.45808210592918697f, k6, a);
            a = fmaf(0.015151515151515152f, k7, a);
            float err = dt_c * a;
            float scale = fmaf(0.01f, fmaxf(fabsf(y), fabsf(y_new)), 0.0001f);
            float q = __fdividef(err, scale);
            float e = q * q;
            e += __shfl_xor_sync(FULLM, e, 8);
            e += __shfl_xor_sync(FULLM, e, 4);
            e += __shfl_xor_sync(FULLM, e, 2);
            e += __shfl_xor_sync(FULLM, e, 1);
            float err2 = fmaxf(e * 0.0625f, 1e-16f);

            bool accept = (err2 <= 1.0f);
            if (accept) { y = y_new; t = t + dt_c; k1 = k7; }
            // factor = clip(0.9 * err2^(-0.1), 0.2, 10)
            float factor = fminf(fmaxf(0.9f * ex2a(-0.1f * lg2a(err2)), 0.2f), 10.0f);
            dt = dt_c * factor;

            // exact freeze: t can only land exactly on 1.0; frozen iterations
            // are bit-exact identities in the reference, so breaking is exact.
            if (__all_sync(FULLM, t >= 1.0f)) break;
        }

        // ---- GRU update with x_t ----
        u64 p[8];
        bcast16(y, p);
        float hr = dot16p(p, whr);
        float hz = dot16p(p, whz);
        float hn = dot16p(p, whn);
        float r = fast_sigmoid(ir + hr);
        float z = fast_sigmoid(iz + hz);
        float n = tanh_pre(fmaf(r, hn + bnv, inn) * (1.0f/TWO_LOG2E) * TWO_LOG2E, 0.0f);
        // NOTE: keep plain form to avoid extra rounding games:
        n = tanh_pre(fmaf(r, hn + bnv, inn), 0.0f);
        y = n + z * (y - n);
    }

    // ---- prediction head: out[b] = dot(h, pred_w) + pred_b ----
    float v = y * pwv;
    v += __shfl_xor_sync(FULLM, v, 8);
    v += __shfl_xor_sync(FULLM, v, 4);
    v += __shfl_xor_sync(FULLM, v, 2);
    v += __shfl_xor_sync(FULLM, v, 1);
    if (l == 0) out[b] = v + pbv;
}

extern "C" void kernel_launch(void* const* d_in, const int* in_sizes, int n_in,
                              void* d_out, int out_size) {
    (void)in_sizes; (void)n_in; (void)out_size;
    ode_rnn_kernel<<<NB/2, 32>>>(
        (const float*)d_in[0],  // x_seq
        (const float*)d_in[1],  (const float*)d_in[2],   // w1 b1
        (const float*)d_in[3],  (const float*)d_in[4],   // w2 b2
        (const float*)d_in[5],  (const float*)d_in[6],   // w3 b3
        (const float*)d_in[7],  (const float*)d_in[8],   // gru_wih gru_whh
        (const float*)d_in[9],  (const float*)d_in[10],  // gru_b gru_bn
        (const float*)d_in[11], (const float*)d_in[12],  // pred_w pred_b
        (float*)d_out);
}

// round 5
// speedup vs baseline: 1.1723x; 1.1723x over previous
#include <cuda_runtime.h>

typedef unsigned long long u64;

#define HID 16
#define TSEQ 64
#define NB 2048
#define MAX_STEPS 16
#define FULLM 0xffffffffu

// ---------------- packed fp32x2 + MUFU helpers ----------------
__device__ __forceinline__ u64 ffma2(u64 a, u64 b, u64 c) {
    u64 d; asm("fma.rn.f32x2 %0, %1, %2, %3;" : "=l"(d) : "l"(a), "l"(b), "l"(c)); return d;
}
__device__ __forceinline__ u64 fmul2(u64 a, u64 b) {
    u64 d; asm("mul.rn.f32x2 %0, %1, %2;" : "=l"(d) : "l"(a), "l"(b)); return d;
}
__device__ __forceinline__ u64 fadd2(u64 a, u64 b) {
    u64 d; asm("add.rn.f32x2 %0, %1, %2;" : "=l"(d) : "l"(a), "l"(b)); return d;
}
__device__ __forceinline__ float2 unpk2(u64 a) {
    float lo, hi; asm("mov.b64 {%0, %1}, %2;" : "=f"(lo), "=f"(hi) : "l"(a));
    return make_float2(lo, hi);
}
__device__ __forceinline__ u64 pk2(float lo, float hi) {
    u64 d; asm("mov.b64 %0, {%1, %2};" : "=l"(d) : "f"(lo), "f"(hi)); return d;
}
__device__ __forceinline__ float ex2a(float x){ float r; asm("ex2.approx.f32 %0, %1;" : "=f"(r) : "f"(x)); return r; }
__device__ __forceinline__ float rcpa(float x){ float r; asm("rcp.approx.f32 %0, %1;" : "=f"(r) : "f"(x)); return r; }
__device__ __forceinline__ float lg2a(float x){ float r; asm("lg2.approx.f32 %0, %1;" : "=f"(r) : "f"(x)); return r; }

#define TWO_LOG2E 2.885390081777927f

// tanh(z + b) with prescaled bias bs = TWO_LOG2E*b
__device__ __forceinline__ float tanh_pre(float z, float bs){
    float e = ex2a(fmaf(z, TWO_LOG2E, bs));
    return fmaf(-2.0f, rcpa(e + 1.0f), 1.0f);
}
__device__ __forceinline__ float fast_tanh(float x){
    float e = ex2a(x * TWO_LOG2E);
    return fmaf(-2.0f, rcpa(e + 1.0f), 1.0f);
}
__device__ __forceinline__ float fast_sigmoid(float x){
    float e = ex2a(x * -1.4426950408889634f);
    return rcpa(e + 1.0f);
}

// dot of 16-float smem vector (16B aligned, broadcast-read) vs packed weight row
__device__ __forceinline__ float dot16s(const float* __restrict__ src, const u64* w){
    const ulonglong2* v = (const ulonglong2*)src;
    ulonglong2 a0 = v[0], a1 = v[1], a2 = v[2], a3 = v[3];
    u64 s0 = fmul2(a0.x, w[0]);
    u64 s1 = fmul2(a0.y, w[1]);
    u64 s2 = fmul2(a1.x, w[2]);
    u64 s3 = fmul2(a1.y, w[3]);
    s0 = ffma2(a2.x, w[4], s0);
    s1 = ffma2(a2.y, w[5], s1);
    s2 = ffma2(a3.x, w[6], s2);
    s3 = ffma2(a3.y, w[7], s3);
    u64 t0 = fadd2(s0, s1);
    u64 t1 = fadd2(s2, s3);
    u64 t2 = fadd2(t0, t1);
    float2 f = unpk2(t2);
    return f.x + f.y;
}

__device__ __forceinline__ void load_row16(const float* __restrict__ base, u64* wp){
    const float4* p = (const float4*)base;
#pragma unroll
    for (int k = 0; k < 4; ++k) {
        float4 f = p[k];
        wp[2*k]   = pk2(f.x, f.y);
        wp[2*k+1] = pk2(f.z, f.w);
    }
}

// One broadcast stage with ping-pong buffers: write own component, sync once,
// dot against packed weights. Swaps cur/alt so consecutive stages alternate
// buffers (WAR hazard ordered by the intervening stage's syncwarp).
__device__ __forceinline__ float stage_dot(float a, int l, float*& cur, float*& alt,
                                           const u64* w){
    cur[l] = a;
    __syncwarp();
    float d = dot16s(cur, w);
    float* tmp = cur; cur = alt; alt = tmp;
    return d;
}

__global__ void __launch_bounds__(32) ode_rnn_kernel(
    const float* __restrict__ x_seq,
    const float* __restrict__ w1, const float* __restrict__ b1,
    const float* __restrict__ w2, const float* __restrict__ b2,
    const float* __restrict__ w3, const float* __restrict__ b3,
    const float* __restrict__ gwih, const float* __restrict__ gwhh,
    const float* __restrict__ gb,  const float* __restrict__ gbn,
    const float* __restrict__ pw,  const float* __restrict__ pb,
    float* __restrict__ out)
{
    const int lane = threadIdx.x;
    const int l = lane & 15;          // hidden component
    const int s = lane >> 4;          // sample within warp (0/1)
    const int b = blockIdx.x * 2 + s;

    // Two 16-float ping-pong buffers per sample. Sample offset 48 floats
    // (48 mod 32 == 16) keeps the two samples' active buffers in disjoint
    // bank halves for every parity -> conflict-free STS/LDS.
    __shared__ __align__(16) float sbuf[2*48];
    float* cur = sbuf + s * 48;
    float* alt = cur + 16;

    // register-resident weights (rows owned by this lane)
    u64 w1p[8], w2p[8], w3p[8], whr[8], whz[8], whn[8];
    load_row16(w1 + l*16, w1p);
    load_row16(w2 + l*16, w2p);
    load_row16(w3 + l*16, w3p);
    load_row16(gwhh + l*16,      whr);
    load_row16(gwhh + (16+l)*16, whz);
    load_row16(gwhh + (32+l)*16, whn);
    const float b1s = b1[l] * TWO_LOG2E;
    const float b2s = b2[l] * TWO_LOG2E;
    const float b3v = b3[l];
    const float wr0 = gwih[l*2],      wr1 = gwih[l*2+1];
    const float wz0 = gwih[(16+l)*2], wz1 = gwih[(16+l)*2+1];
    const float wn0 = gwih[(32+l)*2], wn1 = gwih[(32+l)*2+1];
    const float gbr = gb[l], gbz = gb[16+l], gbnn = gb[32+l];
    const float bnv = gbn[l];
    const float pwv = pw[l];
    const float pbv = pb[0];

    float y = 0.0f;
    const float* xb = x_seq + (size_t)b * (TSEQ*2);

    // f(v) component l: 3 broadcast stages
#define F_EVAL(arg, kout) do {                                              \
        float _h1 = tanh_pre(stage_dot((arg), l, cur, alt, w1p), b1s);      \
        float _h2 = tanh_pre(stage_dot(_h1,  l, cur, alt, w2p), b2s);      \
        kout = stage_dot(_h2, l, cur, alt, w3p) + b3v;                      \
    } while (0)

#pragma unroll 1
    for (int ts = 0; ts < TSEQ; ++ts) {
        const float x0 = xb[ts*2 + 0];
        const float x1 = xb[ts*2 + 1];
        const float ir  = fmaf(x0, wr0, fmaf(x1, wr1, gbr));
        const float iz  = fmaf(x0, wz0, fmaf(x1, wz1, gbz));
        const float inn = fmaf(x0, wn0, fmaf(x1, wn1, gbnn));

        // ---- adaptive Tsit5, t: 0 -> 1 ----
        float t = 0.0f, dt = 1.0f;
        float k1;
        F_EVAL(y, k1);   // FSAL seed; reused across iterations (bit-exact)
#pragma unroll 1
        for (int it = 0; it < MAX_STEPS; ++it) {
            float dt_c = fminf(dt, 1.0f - t);

            float a = 0.161f * k1;
            float k2; F_EVAL(fmaf(dt_c, a, y), k2);
            a = fmaf(0.335480655492357f, k2, -0.008480655492356989f * k1);
            float k3; F_EVAL(fmaf(dt_c, a, y), k3);
            a = 2.8971530571054935f * k1;
            a = fmaf(-6.359448489975075f, k2, a);
            a = fmaf(4.3622954328695815f, k3, a);
            float k4; F_EVAL(fmaf(dt_c, a, y), k4);
            a = 5.325864828439257f * k1;
            a = fmaf(-11.748883564062828f, k2, a);
            a = fmaf(7.4955393428898365f, k3, a);
            a = fmaf(-0.09249506636175525f, k4, a);
            float k5; F_EVAL(fmaf(dt_c, a, y), k5);
            a = 5.86145544294642f * k1;
            a = fmaf(-12.92096931784711f, k2, a);
            a = fmaf(8.159367898576159f, k3, a);
            a = fmaf(-0.071584973281401f, k4, a);
            a = fmaf(-0.028269050394068383f, k5, a);
            float k6; F_EVAL(fmaf(dt_c, a, y), k6);
            a = 0.09646076681806523f * k1;
            a = fmaf(0.01f, k2, a);
            a = fmaf(0.4798896504144996f, k3, a);
            a = fmaf(1.379008574103742f, k4, a);
            a = fmaf(-3.290069515436081f, k5, a);
            a = fmaf(2.324710524099774f, k6, a);
            float y_new = fmaf(dt_c, a, y);
            float k7; F_EVAL(y_new, k7);

            a = -0.001780011052225777f * k1;
            a = fmaf(-0.0008164344596567469f, k2, a);
            a = fmaf(0.007880878010261995f, k3, a);
            a = fmaf(-0.1447110071732629f, k4, a);
            a = fmaf(0.5823571654525552f, k5, a);
            a = fmaf(-0.45808210592918697f, k6, a);
            a = fmaf(0.015151515151515152f, k7, a);
            float err = dt_c * a;
            float scale = fmaf(0.01f, fmaxf(fabsf(y), fabsf(y_new)), 0.0001f);
            float q = __fdividef(err, scale);
            float e = q * q;
            e += __shfl_xor_sync(FULLM, e, 8);
            e += __shfl_xor_sync(FULLM, e, 4);
            e += __shfl_xor_sync(FULLM, e, 2);
            e += __shfl_xor_sync(FULLM, e, 1);
            float err2 = fmaxf(e * 0.0625f, 1e-16f);

            bool accept = (err2 <= 1.0f);
            if (accept) { y = y_new; t = t + dt_c; k1 = k7; }
            float factor = fminf(fmaxf(0.9f * ex2a(-0.1f * lg2a(err2)), 0.2f), 10.0f);
            dt = dt_c * factor;

            // exact freeze: frozen iterations are bit-exact identities
            if (__all_sync(FULLM, t >= 1.0f)) break;
        }

        // ---- GRU update with x_t (broadcast y once, 3 dots off same buffer) ----
        cur[l] = y;
        __syncwarp();
        float hr = dot16s(cur, whr);
        float hz = dot16s(cur, whz);
        float hn = dot16s(cur, whn);
        { float* tmp = cur; cur = alt; alt = tmp; }
        float r = fast_sigmoid(ir + hr);
        float z = fast_sigmoid(iz + hz);
        float n = fast_tanh(fmaf(r, hn + bnv, inn));
        y = n + z * (y - n);
    }

    // ---- prediction head ----
    float v = y * pwv;
    v += __shfl_xor_sync(FULLM, v, 8);
    v += __shfl_xor_sync(FULLM, v, 4);
    v += __shfl_xor_sync(FULLM, v, 2);
    v += __shfl_xor_sync(FULLM, v, 1);
    if (l == 0) out[b] = v + pbv;
#undef F_EVAL
}

extern "C" void kernel_launch(void* const* d_in, const int* in_sizes, int n_in,
                              void* d_out, int out_size) {
    (void)in_sizes; (void)n_in; (void)out_size;
    ode_rnn_kernel<<<NB/2, 32>>>(
        (const float*)d_in[0],
        (const float*)d_in[1],  (const float*)d_in[2],
        (const float*)d_in[3],  (const float*)d_in[4],
        (const float*)d_in[5],  (const float*)d_in[6],
        (const float*)d_in[7],  (const float*)d_in[8],
        (const float*)d_in[9],  (const float*)d_in[10],
        (const float*)d_in[11], (const float*)d_in[12],
        (float*)d_out);
}